// round 10
// baseline (speedup 1.0000x reference)
#include <cuda_runtime.h>
#include <cstdint>

#define THREADS 512
#define TILE_R  128

// ---- SMEM byte offsets ----
#define OFF_V    0        // fp32 V/T: 128 x 132 x 4 = 67584
#define OFF_VB   67584    // bf16 V:   128 x 68 u32  = 34816
#define OFF_H0   102400   // bf16 H buf0: 128 x 36 u32 = 18432
#define OFF_H1   120832   // bf16 H buf1
#define OFF_W1A  139264   // 16384
#define OFF_W1B  155648   // 16384
#define OFF_W2A  172032   // 16384
#define OFF_W2B  188416   // 16384
#define OFF_PAR  204800   // 2560 floats
#define SMEM_BYTES 215040

#define VSTR  132
#define VBSTR 68
#define HSTR  36

// pre-packed bf16 B-fragment weight images, uint4 = two adjacent 8-col n-tiles
// w1img slot (ks*4 + p)*32 + lane : nt = 2p, 2p+1   (K=128, N=64/chunk)
// w2img slot (ks*8 + p)*32 + lane : nt = 2p, 2p+1   (K=64/chunk, N=128)
__device__ uint4 g_w1img[2][8][1024];
__device__ uint4 g_w2img[2][8][1024];

__device__ __forceinline__ uint32_t smem_u32(const void* p){
    uint32_t a;
    asm("{ .reg .u64 t; cvta.to.shared.u64 t, %1; cvt.u32.u64 %0, t; }"
        : "=r"(a) : "l"(p));
    return a;
}
__device__ __forceinline__ uint32_t bf2(float lo, float hi){
    uint32_t r;
    asm("cvt.rn.bf16x2.f32 %0, %1, %2;" : "=r"(r) : "f"(hi), "f"(lo));
    return r;
}
// fast GELU (tanh form)
__device__ __forceinline__ float gelu_fast(float x){
    float t = x * x;
    float s = fmaf(t, 0.10293971f, 2.3021293f);
    float z = x * s;
    float e;
    asm("ex2.approx.f32 %0, %1;" : "=f"(e) : "f"(z));
    float rc;
    asm("rcp.approx.f32 %0, %1;" : "=f"(rc) : "f"(1.0f + e));
    return x - x * rc;
}

#define MMA_BF16(d, a, b0, b1) asm volatile( \
    "mma.sync.aligned.m16n8k16.row.col.f32.bf16.bf16.f32 " \
    "{%0,%1,%2,%3},{%4,%5,%6,%7},{%8,%9},{%0,%1,%2,%3};" \
    : "+f"((d)[0]), "+f"((d)[1]), "+f"((d)[2]), "+f"((d)[3]) \
    : "r"((a)[0]), "r"((a)[1]), "r"((a)[2]), "r"((a)[3]), \
      "r"(b0), "r"(b1))

#define LDSM4(r, addr) asm volatile( \
    "ldmatrix.sync.aligned.m8n8.x4.shared.b16 {%0,%1,%2,%3}, [%4];" \
    : "=r"((r)[0]), "=r"((r)[1]), "=r"((r)[2]), "=r"((r)[3]) : "r"(addr))

#define CP_ASYNC16(dst, src) asm volatile( \
    "cp.async.cg.shared.global [%0], [%1], 16;" :: "r"(dst), "l"(src))
#define CP_COMMIT() asm volatile("cp.async.commit_group;" ::: "memory")
#define CP_WAIT(n)  asm volatile("cp.async.wait_group %0;" :: "n"(n) : "memory")

// stage one 16KB weight image (1024 x 16B) with 512 threads, one commit group
__device__ __forceinline__ void stage16k(uint32_t dst, const void* src, int tid){
    const float4* s4 = (const float4*)src;
    CP_ASYNC16(dst + (uint32_t)tid * 16u, s4 + tid);
    CP_ASYNC16(dst + (uint32_t)(tid + 512) * 16u, s4 + tid + 512);
    CP_COMMIT();
}

// load the full GEMM1 A operand (32 rows x K=128) into registers: 16 LDSM4
__device__ __forceinline__ void load_afrags(uint32_t Afr[2][8][4],
                                            const uint32_t a1ad[2]){
#pragma unroll
    for (int mt = 0; mt < 2; ++mt)
#pragma unroll
        for (int ks = 0; ks < 8; ++ks)
            LDSM4(Afr[mt][ks], a1ad[mt] + ks * 32u);
}

// ---- fused GEMM1 (+ optional GEMM2), A1 register-resident ----
// GEMM1: acc1 = Vb(128x128) @ W1chunk(128x64), warp tile 32x16 (8 k-steps)
// GEMM2: acc2 += H(128x64) @ W2chunk(64x128), warp tile 32x32 (4 k-steps)
__device__ __forceinline__ void gemm12(float acc1[2][2][4], float acc2[2][4][4],
                                       const uint32_t Afr[2][8][4],
                                       const uint32_t a2ad[2],
                                       const uint4* __restrict__ w1,
                                       const uint4* __restrict__ w2,
                                       int wc, int lane, bool doG2){
#pragma unroll
    for (int a = 0; a < 2; ++a)
#pragma unroll
        for (int b = 0; b < 2; ++b)
#pragma unroll
            for (int d = 0; d < 4; ++d) acc1[a][b][d] = 0.f;
    const uint4* bp1 = w1 + wc * 32 + lane;
    const uint4* bp2 = w2 + (wc * 2) * 32 + lane;
#pragma unroll
    for (int s = 0; s < 4; ++s){
#pragma unroll
        for (int kk = 0; kk < 2; ++kk){
            const int ks = 2 * s + kk;
            uint4 B = bp1[ks * 128];
            MMA_BF16(acc1[0][0], Afr[0][ks], B.x, B.y);
            MMA_BF16(acc1[0][1], Afr[0][ks], B.z, B.w);
            MMA_BF16(acc1[1][0], Afr[1][ks], B.x, B.y);
            MMA_BF16(acc1[1][1], Afr[1][ks], B.z, B.w);
        }
        if (doG2){
            uint32_t A0[4], A1[4];
            LDSM4(A0, a2ad[0] + s * 32u);
            LDSM4(A1, a2ad[1] + s * 32u);
            uint4 Ba = bp2[s * 256], Bb = bp2[s * 256 + 32];
            MMA_BF16(acc2[0][0], A0, Ba.x, Ba.y);
            MMA_BF16(acc2[1][0], A1, Ba.x, Ba.y);
            MMA_BF16(acc2[0][1], A0, Ba.z, Ba.w);
            MMA_BF16(acc2[1][1], A1, Ba.z, Ba.w);
            MMA_BF16(acc2[0][2], A0, Bb.x, Bb.y);
            MMA_BF16(acc2[1][2], A1, Bb.x, Bb.y);
            MMA_BF16(acc2[0][3], A0, Bb.z, Bb.w);
            MMA_BF16(acc2[1][3], A1, Bb.z, Bb.w);
        }
    }
}

__device__ __forceinline__ void gemm2_only(float acc2[2][4][4],
                                           const uint32_t a2ad[2],
                                           const uint4* __restrict__ w2,
                                           int wc, int lane){
    const uint4* bp2 = w2 + (wc * 2) * 32 + lane;
#pragma unroll
    for (int s = 0; s < 4; ++s){
        uint32_t A0[4], A1[4];
        LDSM4(A0, a2ad[0] + s * 32u);
        LDSM4(A1, a2ad[1] + s * 32u);
        uint4 Ba = bp2[s * 256], Bb = bp2[s * 256 + 32];
        MMA_BF16(acc2[0][0], A0, Ba.x, Ba.y);
        MMA_BF16(acc2[1][0], A1, Ba.x, Ba.y);
        MMA_BF16(acc2[0][1], A0, Ba.z, Ba.w);
        MMA_BF16(acc2[1][1], A1, Ba.z, Ba.w);
        MMA_BF16(acc2[0][2], A0, Bb.x, Bb.y);
        MMA_BF16(acc2[1][2], A1, Bb.x, Bb.y);
        MMA_BF16(acc2[0][3], A0, Bb.z, Bb.w);
        MMA_BF16(acc2[1][3], A1, Bb.z, Bb.w);
    }
}

// ---- epilogue: bias + fast GELU -> sH buffer (bf16) ----
__device__ __forceinline__ void epi1(const float acc1[2][2][4],
                                     uint32_t* __restrict__ sHb,
                                     const float* __restrict__ pB1,
                                     int wr, int wc, int qrow, int qcol){
#pragma unroll
    for (int mt = 0; mt < 2; ++mt){
        const int rb = wr * 32 + mt * 16 + qrow;
#pragma unroll
        for (int ntl = 0; ntl < 2; ++ntl){
            const int cb = wc * 16 + ntl * 8 + 2 * qcol;
            const float bz0 = pB1[cb], bz1 = pB1[cb + 1];
            sHb[rb * HSTR + (cb >> 1)] =
                bf2(gelu_fast(acc1[mt][ntl][0] + bz0),
                    gelu_fast(acc1[mt][ntl][1] + bz1));
            sHb[(rb + 8) * HSTR + (cb >> 1)] =
                bf2(gelu_fast(acc1[mt][ntl][2] + bz0),
                    gelu_fast(acc1[mt][ntl][3] + bz1));
        }
    }
}

// ---------------- prep: pack bf16 uint4 B-fragment weight images ----------------
__global__ void prep_kernel(const float* __restrict__ W1a, const float* __restrict__ W2a,
                            const float* __restrict__ W1b, const float* __restrict__ W2b)
{
    int idx  = blockIdx.x * 256 + threadIdx.x;   // 0..32767
    int isW2 = idx >> 14;
    int r    = idx & 16383;
    int m    = r >> 13;
    int c    = (r >> 10) & 7;
    int s    = r & 1023;
    int lane = s & 31;
    int t    = s >> 5;                            // 0..31
    if (!isW2){
        int ks = t >> 2, p = t & 3;
        const float* W1 = m ? W1b : W1a;
        int k  = ks * 16 + (lane & 3) * 2;
        int n0 = c * 64 + (2 * p) * 8 + (lane >> 2);
        int n1 = n0 + 8;
        uint4 v;
        v.x = bf2(W1[(size_t)k * 512 + n0],       W1[(size_t)(k + 1) * 512 + n0]);
        v.y = bf2(W1[(size_t)(k + 8) * 512 + n0], W1[(size_t)(k + 9) * 512 + n0]);
        v.z = bf2(W1[(size_t)k * 512 + n1],       W1[(size_t)(k + 1) * 512 + n1]);
        v.w = bf2(W1[(size_t)(k + 8) * 512 + n1], W1[(size_t)(k + 9) * 512 + n1]);
        g_w1img[m][c][s] = v;
    } else {
        int ks = t >> 3, p = t & 7;
        const float* W2 = m ? W2b : W2a;
        int k  = c * 64 + ks * 16 + (lane & 3) * 2;
        int n0 = (2 * p) * 8 + (lane >> 2);
        int n1 = n0 + 8;
        uint4 v;
        v.x = bf2(W2[(size_t)k * 128 + n0],       W2[(size_t)(k + 1) * 128 + n0]);
        v.y = bf2(W2[(size_t)(k + 8) * 128 + n0], W2[(size_t)(k + 9) * 128 + n0]);
        v.z = bf2(W2[(size_t)k * 128 + n1],       W2[(size_t)(k + 1) * 128 + n1]);
        v.w = bf2(W2[(size_t)(k + 8) * 128 + n1], W2[(size_t)(k + 9) * 128 + n1]);
        g_w2img[m][c][s] = v;
    }
}

// ---------------- main kernel ----------------
extern "C" __global__ void __launch_bounds__(THREADS, 1)
tsal_areg_kernel(const float* __restrict__ x,
                 const float* __restrict__ bo_time, const float* __restrict__ bo_recv,
                 const float* __restrict__ g1, const float* __restrict__ be1,
                 const float* __restrict__ g2, const float* __restrict__ be2,
                 const float* __restrict__ g3, const float* __restrict__ be3,
                 const float* __restrict__ g4, const float* __restrict__ be4,
                 const float* __restrict__ b1a, const float* __restrict__ b2a,
                 const float* __restrict__ b1b, const float* __restrict__ b2b,
                 float* __restrict__ out)
{
    extern __shared__ __align__(16) char smb[];
    float*    sV  = (float*)(smb + OFF_V);
    uint32_t* sVb = (uint32_t*)(smb + OFF_VB);
    float*    par = (float*)(smb + OFF_PAR);
    uint32_t* sHbuf[2] = { (uint32_t*)(smb + OFF_H0), (uint32_t*)(smb + OFF_H1) };
    const uint4* w1buf[2] = { (const uint4*)(smb + OFF_W1A), (const uint4*)(smb + OFF_W1B) };
    const uint4* w2buf[2] = { (const uint4*)(smb + OFF_W2A), (const uint4*)(smb + OFF_W2B) };
    const uint32_t w1addr[2] = { smem_u32(smb + OFF_W1A), smem_u32(smb + OFF_W1B) };
    const uint32_t w2addr[2] = { smem_u32(smb + OFF_W2A), smem_u32(smb + OFF_W2B) };

    const int tid  = threadIdx.x;
    const int lane = tid & 31, wid = tid >> 5;
    const int wr   = wid & 3, wc = wid >> 2;     // warp grid: 4 rows x 4 cols
    const int qrow = lane >> 2, qcol = lane & 3;
    const int lrow = tid >> 2, lq = tid & 3;     // LN: 4 threads/row

    // ldmatrix per-lane source coordinates (m16k16 .x4)
    const int lmRow = ((lane >> 3) & 1) * 8 + (lane & 7);
    const int lmCol = (lane >> 4) * 4;           // u32 offset
    uint32_t a1ad[2], a2ad[2][2];
    {
        const uint32_t vbA = smem_u32(sVb);
#pragma unroll
        for (int mt = 0; mt < 2; ++mt){
            int row = wr * 32 + mt * 16 + lmRow;
            a1ad[mt]    = vbA + (uint32_t)(row * VBSTR + lmCol) * 4u;
            a2ad[0][mt] = smem_u32(sHbuf[0]) + (uint32_t)(row * HSTR + lmCol) * 4u;
            a2ad[1][mt] = smem_u32(sHbuf[1]) + (uint32_t)(row * HSTR + lmCol) * 4u;
        }
    }

    // prefetch W1[0], W2[0], W1[1]
    stage16k(w1addr[0], &g_w1img[0][0][0], tid);
    stage16k(w2addr[0], &g_w2img[0][0][0], tid);
    stage16k(w1addr[1], &g_w1img[0][1][0], tid);

    // stage params
    for (int i = tid; i < 128; i += THREADS){
        par[i]        = bo_time[i]; par[128 + i]  = bo_recv[i];
        par[256 + i]  = g1[i];      par[384 + i]  = be1[i];
        par[512 + i]  = g2[i];      par[640 + i]  = be2[i];
        par[768 + i]  = g3[i];      par[896 + i]  = be3[i];
        par[1024 + i] = g4[i];      par[1152 + i] = be4[i];
        par[1280 + i] = b2a[i];     par[1408 + i] = b2b[i];
    }
    for (int i = tid; i < 512; i += THREADS){
        par[1536 + i] = b1a[i];     par[2048 + i] = b1b[i];
    }
    __syncthreads();

    // ---- LN1: v1 = LN(x + bo_time) -> sV (fp32) + sVb (bf16) ----
    const size_t grow = (size_t)blockIdx.x * TILE_R + lrow;
    {
        float4 v[8];
        float s = 0.f, q = 0.f;
#pragma unroll
        for (int i = 0; i < 8; ++i){
            int c = 16 * i + 4 * lq;
            float4 a = *(const float4*)(x + grow * 128 + c);
            a.x += par[c + 0]; a.y += par[c + 1]; a.z += par[c + 2]; a.w += par[c + 3];
            v[i] = a;
            s += a.x + a.y + a.z + a.w;
            q = fmaf(a.x, a.x, q); q = fmaf(a.y, a.y, q);
            q = fmaf(a.z, a.z, q); q = fmaf(a.w, a.w, q);
        }
        s += __shfl_xor_sync(0xffffffffu, s, 1, 4); s += __shfl_xor_sync(0xffffffffu, s, 2, 4);
        q += __shfl_xor_sync(0xffffffffu, q, 1, 4); q += __shfl_xor_sync(0xffffffffu, q, 2, 4);
        float mu = s * 0.0078125f;
        float rs = rsqrtf(q * 0.0078125f - mu * mu + 1e-5f);
#pragma unroll
        for (int i = 0; i < 8; ++i){
            int c = 16 * i + 4 * lq;
            float4 a = v[i], o;
            o.x = (a.x - mu) * rs * par[256 + c + 0] + par[384 + c + 0];
            o.y = (a.y - mu) * rs * par[256 + c + 1] + par[384 + c + 1];
            o.z = (a.z - mu) * rs * par[256 + c + 2] + par[384 + c + 2];
            o.w = (a.w - mu) * rs * par[256 + c + 3] + par[384 + c + 3];
            *(float4*)(sV + lrow * VSTR + c) = o;
            sVb[lrow * VBSTR + (c >> 1)]     = bf2(o.x, o.y);
            sVb[lrow * VBSTR + (c >> 1) + 1] = bf2(o.z, o.w);
        }
    }

    float acc2[2][4][4];
#pragma unroll
    for (int a = 0; a < 2; ++a)
#pragma unroll
        for (int b = 0; b < 4; ++b)
#pragma unroll
            for (int d = 0; d < 4; ++d) acc2[a][b][d] = 0.f;

    uint32_t Afr[2][8][4];   // GEMM1 A operand, register-resident per MLP

    // ---- preamble: GEMM1[0] + epilogue -> sH[0] ----
    CP_WAIT(2);          // W1[0] resident
    __syncthreads();     // sVb visible
    load_afrags(Afr, a1ad);
    {
        float acc1[2][2][4];
        gemm12(acc1, acc2, Afr, a2ad[0], w1buf[0], w2buf[0], wc, lane, false);
        epi1(acc1, sHbuf[0], par + 1536, wr, wc, qrow, qcol);
    }

    // ---- 16 phases: phase p runs GEMM1[p+1] fused with GEMM2[p] ----
    for (int p = 0; p < 16; ++p){
        __syncthreads();   // sH[p&1] writes visible; frees weight buffers
        if (p <= 14) stage16k(w2addr[(p + 1) & 1], &g_w2img[(p + 1) >> 3][(p + 1) & 7][0], tid);
        if (p <= 13) stage16k(w1addr[p & 1],       &g_w1img[(p + 2) >> 3][(p + 2) & 7][0], tid);
        if (p <= 13)      CP_WAIT(2);
        else if (p == 14) CP_WAIT(1);
        else              CP_WAIT(0);

        const int ch = p & 7;
        if (ch != 7){
            const int q = p + 1;
            float acc1[2][2][4];
            gemm12(acc1, acc2, Afr, a2ad[p & 1], w1buf[q & 1], w2buf[p & 1],
                   wc, lane, true);
            epi1(acc1, sHbuf[q & 1],
                 par + ((q >= 8) ? 2048 : 1536) + (q & 7) * 64, wr, wc, qrow, qcol);
        } else {
            // boundary: finish this MLP, run LN chain, then start next MLP's GEMM1
            gemm2_only(acc2, a2ad[1], w2buf[1], wc, lane);
            const float* pB2 = par + ((p >= 8) ? 1408 : 1280);
            // T = V + D2 + b2, in place in sV
#pragma unroll
            for (int mt = 0; mt < 2; ++mt){
                const int rb = wr * 32 + mt * 16 + qrow;
#pragma unroll
                for (int ntl = 0; ntl < 4; ++ntl){
                    const int cb = wc * 32 + ntl * 8 + 2 * qcol;
                    const float b20 = pB2[cb], b21 = pB2[cb + 1];
                    float2* v0p = (float2*)(sV + rb * VSTR + cb);
                    float2* v1p = (float2*)(sV + (rb + 8) * VSTR + cb);
                    float2 v0 = *v0p, v1 = *v1p;
                    v0.x += acc2[mt][ntl][0] + b20; v0.y += acc2[mt][ntl][1] + b21;
                    v1.x += acc2[mt][ntl][2] + b20; v1.y += acc2[mt][ntl][3] + b21;
                    *v0p = v0; *v1p = v1;
                }
            }
            __syncthreads();

            // LN on T rows (4 threads/row)
            float4 v[8];
            float s = 0.f, q = 0.f;
#pragma unroll
            for (int i = 0; i < 8; ++i){
                int c = 16 * i + 4 * lq;
                float4 a = *(const float4*)(sV + lrow * VSTR + c);
                v[i] = a;
                s += a.x + a.y + a.z + a.w;
                q = fmaf(a.x, a.x, q); q = fmaf(a.y, a.y, q);
                q = fmaf(a.z, a.z, q); q = fmaf(a.w, a.w, q);
            }
            s += __shfl_xor_sync(0xffffffffu, s, 1, 4); s += __shfl_xor_sync(0xffffffffu, s, 2, 4);
            q += __shfl_xor_sync(0xffffffffu, q, 1, 4); q += __shfl_xor_sync(0xffffffffu, q, 2, 4);
            float mu = s * 0.0078125f;
            float rs = rsqrtf(q * 0.0078125f - mu * mu + 1e-5f);

            if (p == 7){
                float s2 = 0.f, q2 = 0.f;
#pragma unroll
                for (int i = 0; i < 8; ++i){
                    int c = 16 * i + 4 * lq;
                    float4 a = v[i], o;
                    o.x = (a.x - mu) * rs * par[512 + c + 0] + par[640 + c + 0] + par[128 + c + 0];
                    o.y = (a.y - mu) * rs * par[512 + c + 1] + par[640 + c + 1] + par[128 + c + 1];
                    o.z = (a.z - mu) * rs * par[512 + c + 2] + par[640 + c + 2] + par[128 + c + 2];
                    o.w = (a.w - mu) * rs * par[512 + c + 3] + par[640 + c + 3] + par[128 + c + 3];
                    v[i] = o;
                    s2 += o.x + o.y + o.z + o.w;
                    q2 = fmaf(o.x, o.x, q2); q2 = fmaf(o.y, o.y, q2);
                    q2 = fmaf(o.z, o.z, q2); q2 = fmaf(o.w, o.w, q2);
                }
                s2 += __shfl_xor_sync(0xffffffffu, s2, 1, 4); s2 += __shfl_xor_sync(0xffffffffu, s2, 2, 4);
                q2 += __shfl_xor_sync(0xffffffffu, q2, 1, 4); q2 += __shfl_xor_sync(0xffffffffu, q2, 2, 4);
                float mu2 = s2 * 0.0078125f;
                float rs2 = rsqrtf(q2 * 0.0078125f - mu2 * mu2 + 1e-5f);
#pragma unroll
                for (int i = 0; i < 8; ++i){
                    int c = 16 * i + 4 * lq;
                    float4 a = v[i], o;
                    o.x = (a.x - mu2) * rs2 * par[768 + c + 0] + par[896 + c + 0];
                    o.y = (a.y - mu2) * rs2 * par[768 + c + 1] + par[896 + c + 1];
                    o.z = (a.z - mu2) * rs2 * par[768 + c + 2] + par[896 + c + 2];
                    o.w = (a.w - mu2) * rs2 * par[768 + c + 3] + par[896 + c + 3];
                    *(float4*)(sV + lrow * VSTR + c) = o;
                    sVb[lrow * VBSTR + (c >> 1)]     = bf2(o.x, o.y);
                    sVb[lrow * VBSTR + (c >> 1) + 1] = bf2(o.z, o.w);
                }
                __syncthreads();   // sVb ready for mlp1's GEMM1

#pragma unroll
                for (int a = 0; a < 2; ++a)
#pragma unroll
                    for (int b = 0; b < 4; ++b)
#pragma unroll
                        for (int d = 0; d < 4; ++d) acc2[a][b][d] = 0.f;
                load_afrags(Afr, a1ad);   // new V -> reload resident A
                float acc1[2][2][4];
                gemm12(acc1, acc2, Afr, a2ad[0], w1buf[0], w2buf[0], wc, lane, false);
                epi1(acc1, sHbuf[0], par + 2048, wr, wc, qrow, qcol);
            } else {
                // p == 15: out = LN4(T) -> GMEM
#pragma unroll
                for (int i = 0; i < 8; ++i){
                    int c = 16 * i + 4 * lq;
                    float4 a = v[i], o;
                    o.x = (a.x - mu) * rs * par[1024 + c + 0] + par[1152 + c + 0];
                    o.y = (a.y - mu) * rs * par[1024 + c + 1] + par[1152 + c + 1];
                    o.z = (a.z - mu) * rs * par[1024 + c + 2] + par[1152 + c + 2];
                    o.w = (a.w - mu) * rs * par[1024 + c + 3] + par[1152 + c + 3];
                    *(float4*)(out + grow * 128 + c) = o;
                }
            }
        }
    }
}

extern "C" void kernel_launch(void* const* d_in, const int* in_sizes, int n_in,
                              void* d_out, int out_size)
{
    const float* x       = (const float*)d_in[0];
    // d_in[1]=router (dead), d_in[3]=bo_send (dead)
    const float* bo_time = (const float*)d_in[2];
    const float* bo_recv = (const float*)d_in[4];
    const float* g1 = (const float*)d_in[5],  *be1 = (const float*)d_in[6];
    const float* g2 = (const float*)d_in[7],  *be2 = (const float*)d_in[8];
    const float* g3 = (const float*)d_in[9],  *be3 = (const float*)d_in[10];
    const float* g4 = (const float*)d_in[11], *be4 = (const float*)d_in[12];
    const float* W1a = (const float*)d_in[13], *b1a = (const float*)d_in[14];
    const float* W2a = (const float*)d_in[15], *b2a = (const float*)d_in[16];
    const float* W1b = (const float*)d_in[17], *b1b = (const float*)d_in[18];
    const float* W2b = (const float*)d_in[19], *b2b = (const float*)d_in[20];
    float* out = (float*)d_out;

    int rows   = in_sizes[0] / 128;   // 131072
    int blocks = rows / TILE_R;       // 1024

    prep_kernel<<<128, 256>>>(W1a, W2a, W1b, W2b);

    cudaFuncSetAttribute(tsal_areg_kernel,
                         cudaFuncAttributeMaxDynamicSharedMemorySize, SMEM_BYTES);
    tsal_areg_kernel<<<blocks, THREADS, SMEM_BYTES>>>(
        x, bo_time, bo_recv,
        g1, be1, g2, be2, g3, be3, g4, be4,
        b1a, b2a, b1b, b2b, out);
}

// round 11
// speedup vs baseline: 1.1308x; 1.1308x over previous
#include <cuda_runtime.h>
#include <cstdint>

#define THREADS 256
#define TILE_R  128

// ---- SMEM byte offsets ----
#define OFF_V    0        // fp32 V/T: 128 x 132 x 4 = 67584
#define OFF_VB   67584    // bf16 V:   128 x 68 u32  = 34816
#define OFF_H0   102400   // bf16 H buf0: 128 x 36 u32 = 18432
#define OFF_H1   120832   // bf16 H buf1
#define OFF_W1A  139264   // 16384
#define OFF_W1B  155648   // 16384
#define OFF_W2A  172032   // 16384
#define OFF_W2B  188416   // 16384
#define OFF_PAR  204800   // 2560 floats
#define SMEM_BYTES 215040

#define VSTR  132
#define VBSTR 68
#define HSTR  36

// pre-packed bf16 B-fragment weight images, uint4 = two adjacent 8-col n-tiles
// w1img slot (ks*4 + p)*32 + lane : p covers cols p*16..p*16+15   (K=128, N=64/chunk)
// w2img slot (ks*8 + p)*32 + lane : p covers cols p*16..p*16+15   (K=64/chunk, N=128)
__device__ uint4 g_w1img[2][8][1024];
__device__ uint4 g_w2img[2][8][1024];

__device__ __forceinline__ uint32_t smem_u32(const void* p){
    uint32_t a;
    asm("{ .reg .u64 t; cvta.to.shared.u64 t, %1; cvt.u32.u64 %0, t; }"
        : "=r"(a) : "l"(p));
    return a;
}
__device__ __forceinline__ uint32_t bf2(float lo, float hi){
    uint32_t r;
    asm("cvt.rn.bf16x2.f32 %0, %1, %2;" : "=r"(r) : "f"(hi), "f"(lo));
    return r;
}
// fast GELU (tanh form)
__device__ __forceinline__ float gelu_fast(float x){
    float t = x * x;
    float s = fmaf(t, 0.10293971f, 2.3021293f);
    float z = x * s;
    float e;
    asm("ex2.approx.f32 %0, %1;" : "=f"(e) : "f"(z));
    float rc;
    asm("rcp.approx.f32 %0, %1;" : "=f"(rc) : "f"(1.0f + e));
    return x - x * rc;
}

#define MMA_BF16(d, a, b0, b1) asm volatile( \
    "mma.sync.aligned.m16n8k16.row.col.f32.bf16.bf16.f32 " \
    "{%0,%1,%2,%3},{%4,%5,%6,%7},{%8,%9},{%0,%1,%2,%3};" \
    : "+f"((d)[0]), "+f"((d)[1]), "+f"((d)[2]), "+f"((d)[3]) \
    : "r"((a)[0]), "r"((a)[1]), "r"((a)[2]), "r"((a)[3]), \
      "r"(b0), "r"(b1))

#define LDSM4(r, addr) asm volatile( \
    "ldmatrix.sync.aligned.m8n8.x4.shared.b16 {%0,%1,%2,%3}, [%4];" \
    : "=r"((r)[0]), "=r"((r)[1]), "=r"((r)[2]), "=r"((r)[3]) : "r"(addr))

#define CP_ASYNC16(dst, src) asm volatile( \
    "cp.async.cg.shared.global [%0], [%1], 16;" :: "r"(dst), "l"(src))
#define CP_COMMIT() asm volatile("cp.async.commit_group;" ::: "memory")
#define CP_WAIT(n)  asm volatile("cp.async.wait_group %0;" :: "n"(n) : "memory")

// stage one 16KB weight image (1024 x 16B) with 256 threads, one commit group
__device__ __forceinline__ void stage16k(uint32_t dst, const void* src, int tid){
    const float4* s4 = (const float4*)src;
    CP_ASYNC16(dst + (uint32_t)tid * 16u,          s4 + tid);
    CP_ASYNC16(dst + (uint32_t)(tid + 256) * 16u,  s4 + tid + 256);
    CP_ASYNC16(dst + (uint32_t)(tid + 512) * 16u,  s4 + tid + 512);
    CP_ASYNC16(dst + (uint32_t)(tid + 768) * 16u,  s4 + tid + 768);
    CP_COMMIT();
}

// load the full GEMM1 A operand (32 rows x K=128) into registers: 16 LDSM4
__device__ __forceinline__ void load_afrags(uint32_t Afr[2][8][4],
                                            const uint32_t a1ad[2]){
#pragma unroll
    for (int mt = 0; mt < 2; ++mt)
#pragma unroll
        for (int ks = 0; ks < 8; ++ks)
            LDSM4(Afr[mt][ks], a1ad[mt] + ks * 32u);
}

// ---- fused GEMM1 (+ optional GEMM2), A1 register-resident ----
// GEMM1: acc1 = Vb(128x128) @ W1chunk(128x64), warp tile 32x32 (8 k-steps)
// GEMM2: acc2 += H(128x64) @ W2chunk(64x128), warp tile 32x64 (4 k-steps)
__device__ __forceinline__ void gemm12(float acc1[2][4][4], float acc2[2][8][4],
                                       const uint32_t Afr[2][8][4],
                                       const uint32_t a2ad[2],
                                       const uint4* __restrict__ w1,
                                       const uint4* __restrict__ w2,
                                       int wc, int lane, bool doG2){
#pragma unroll
    for (int a = 0; a < 2; ++a)
#pragma unroll
        for (int b = 0; b < 4; ++b)
#pragma unroll
            for (int d = 0; d < 4; ++d) acc1[a][b][d] = 0.f;
    const uint4* bp1 = w1 + (wc * 2) * 32 + lane;
    const uint4* bp2 = w2 + (wc * 4) * 32 + lane;
#pragma unroll
    for (int s = 0; s < 4; ++s){
#pragma unroll
        for (int kk = 0; kk < 2; ++kk){
            const int ks = 2 * s + kk;
            uint4 B0 = bp1[ks * 128];
            uint4 B1 = bp1[ks * 128 + 32];
            MMA_BF16(acc1[0][0], Afr[0][ks], B0.x, B0.y);
            MMA_BF16(acc1[1][0], Afr[1][ks], B0.x, B0.y);
            MMA_BF16(acc1[0][1], Afr[0][ks], B0.z, B0.w);
            MMA_BF16(acc1[1][1], Afr[1][ks], B0.z, B0.w);
            MMA_BF16(acc1[0][2], Afr[0][ks], B1.x, B1.y);
            MMA_BF16(acc1[1][2], Afr[1][ks], B1.x, B1.y);
            MMA_BF16(acc1[0][3], Afr[0][ks], B1.z, B1.w);
            MMA_BF16(acc1[1][3], Afr[1][ks], B1.z, B1.w);
        }
        if (doG2){
            uint32_t A0[4], A1[4];
            LDSM4(A0, a2ad[0] + s * 32u);
            LDSM4(A1, a2ad[1] + s * 32u);
#pragma unroll
            for (int q = 0; q < 4; ++q){
                uint4 B = bp2[s * 256 + q * 32];
                MMA_BF16(acc2[0][2*q],   A0, B.x, B.y);
                MMA_BF16(acc2[1][2*q],   A1, B.x, B.y);
                MMA_BF16(acc2[0][2*q+1], A0, B.z, B.w);
                MMA_BF16(acc2[1][2*q+1], A1, B.z, B.w);
            }
        }
    }
}

__device__ __forceinline__ void gemm2_only(float acc2[2][8][4],
                                           const uint32_t a2ad[2],
                                           const uint4* __restrict__ w2,
                                           int wc, int lane){
    const uint4* bp2 = w2 + (wc * 4) * 32 + lane;
#pragma unroll
    for (int s = 0; s < 4; ++s){
        uint32_t A0[4], A1[4];
        LDSM4(A0, a2ad[0] + s * 32u);
        LDSM4(A1, a2ad[1] + s * 32u);
#pragma unroll
        for (int q = 0; q < 4; ++q){
            uint4 B = bp2[s * 256 + q * 32];
            MMA_BF16(acc2[0][2*q],   A0, B.x, B.y);
            MMA_BF16(acc2[1][2*q],   A1, B.x, B.y);
            MMA_BF16(acc2[0][2*q+1], A0, B.z, B.w);
            MMA_BF16(acc2[1][2*q+1], A1, B.z, B.w);
        }
    }
}

// ---- epilogue: bias + fast GELU -> sH buffer (bf16), warp tile 32x32 ----
__device__ __forceinline__ void epi1(const float acc1[2][4][4],
                                     uint32_t* __restrict__ sHb,
                                     const float* __restrict__ pB1,
                                     int wr, int wc, int qrow, int qcol){
#pragma unroll
    for (int mt = 0; mt < 2; ++mt){
        const int rb = wr * 32 + mt * 16 + qrow;
#pragma unroll
        for (int ntl = 0; ntl < 4; ++ntl){
            const int cb = wc * 32 + ntl * 8 + 2 * qcol;
            const float bz0 = pB1[cb], bz1 = pB1[cb + 1];
            sHb[rb * HSTR + (cb >> 1)] =
                bf2(gelu_fast(acc1[mt][ntl][0] + bz0),
                    gelu_fast(acc1[mt][ntl][1] + bz1));
            sHb[(rb + 8) * HSTR + (cb >> 1)] =
                bf2(gelu_fast(acc1[mt][ntl][2] + bz0),
                    gelu_fast(acc1[mt][ntl][3] + bz1));
        }
    }
}

// ---------------- prep: pack bf16 uint4 B-fragment weight images ----------------
__global__ void prep_kernel(const float* __restrict__ W1a, const float* __restrict__ W2a,
                            const float* __restrict__ W1b, const float* __restrict__ W2b)
{
    int idx  = blockIdx.x * 256 + threadIdx.x;   // 0..32767
    int isW2 = idx >> 14;
    int r    = idx & 16383;
    int m    = r >> 13;
    int c    = (r >> 10) & 7;
    int s    = r & 1023;
    int lane = s & 31;
    int t    = s >> 5;                            // 0..31
    if (!isW2){
        int ks = t >> 2, p = t & 3;
        const float* W1 = m ? W1b : W1a;
        int k  = ks * 16 + (lane & 3) * 2;
        int n0 = c * 64 + (2 * p) * 8 + (lane >> 2);
        int n1 = n0 + 8;
        uint4 v;
        v.x = bf2(W1[(size_t)k * 512 + n0],       W1[(size_t)(k + 1) * 512 + n0]);
        v.y = bf2(W1[(size_t)(k + 8) * 512 + n0], W1[(size_t)(k + 9) * 512 + n0]);
        v.z = bf2(W1[(size_t)k * 512 + n1],       W1[(size_t)(k + 1) * 512 + n1]);
        v.w = bf2(W1[(size_t)(k + 8) * 512 + n1], W1[(size_t)(k + 9) * 512 + n1]);
        g_w1img[m][c][s] = v;
    } else {
        int ks = t >> 3, p = t & 7;
        const float* W2 = m ? W2b : W2a;
        int k  = c * 64 + ks * 16 + (lane & 3) * 2;
        int n0 = (2 * p) * 8 + (lane >> 2);
        int n1 = n0 + 8;
        uint4 v;
        v.x = bf2(W2[(size_t)k * 128 + n0],       W2[(size_t)(k + 1) * 128 + n0]);
        v.y = bf2(W2[(size_t)(k + 8) * 128 + n0], W2[(size_t)(k + 9) * 128 + n0]);
        v.z = bf2(W2[(size_t)k * 128 + n1],       W2[(size_t)(k + 1) * 128 + n1]);
        v.w = bf2(W2[(size_t)(k + 8) * 128 + n1], W2[(size_t)(k + 9) * 128 + n1]);
        g_w2img[m][c][s] = v;
    }
}

// ---------------- main kernel ----------------
extern "C" __global__ void __launch_bounds__(THREADS, 1)
tsal_big_kernel(const float* __restrict__ x,
                const float* __restrict__ bo_time, const float* __restrict__ bo_recv,
                const float* __restrict__ g1, const float* __restrict__ be1,
                const float* __restrict__ g2, const float* __restrict__ be2,
                const float* __restrict__ g3, const float* __restrict__ be3,
                const float* __restrict__ g4, const float* __restrict__ be4,
                const float* __restrict__ b1a, const float* __restrict__ b2a,
                const float* __restrict__ b1b, const float* __restrict__ b2b,
                float* __restrict__ out)
{
    extern __shared__ __align__(16) char smb[];
    float*    sV  = (float*)(smb + OFF_V);
    uint32_t* sVb = (uint32_t*)(smb + OFF_VB);
    float*    par = (float*)(smb + OFF_PAR);
    uint32_t* sHbuf[2] = { (uint32_t*)(smb + OFF_H0), (uint32_t*)(smb + OFF_H1) };
    const uint4* w1buf[2] = { (const uint4*)(smb + OFF_W1A), (const uint4*)(smb + OFF_W1B) };
    const uint4* w2buf[2] = { (const uint4*)(smb + OFF_W2A), (const uint4*)(smb + OFF_W2B) };
    const uint32_t w1addr[2] = { smem_u32(smb + OFF_W1A), smem_u32(smb + OFF_W1B) };
    const uint32_t w2addr[2] = { smem_u32(smb + OFF_W2A), smem_u32(smb + OFF_W2B) };

    const int tid  = threadIdx.x;
    const int lane = tid & 31, wid = tid >> 5;
    const int wr   = wid & 3, wc = wid >> 2;     // warp grid: 4 rows x 2 cols
    const int qrow = lane >> 2, qcol = lane & 3;
    const int lrow = tid >> 1, lhalf = tid & 1;  // LN: 2 threads/row

    // ldmatrix per-lane source coordinates (m16k16 .x4)
    const int lmRow = ((lane >> 3) & 1) * 8 + (lane & 7);
    const int lmCol = (lane >> 4) * 4;           // u32 offset
    uint32_t a1ad[2], a2ad[2][2];
    {
        const uint32_t vbA = smem_u32(sVb);
#pragma unroll
        for (int mt = 0; mt < 2; ++mt){
            int row = wr * 32 + mt * 16 + lmRow;
            a1ad[mt]    = vbA + (uint32_t)(row * VBSTR + lmCol) * 4u;
            a2ad[0][mt] = smem_u32(sHbuf[0]) + (uint32_t)(row * HSTR + lmCol) * 4u;
            a2ad[1][mt] = smem_u32(sHbuf[1]) + (uint32_t)(row * HSTR + lmCol) * 4u;
        }
    }

    // prefetch W1[0], W2[0], W1[1]
    stage16k(w1addr[0], &g_w1img[0][0][0], tid);
    stage16k(w2addr[0], &g_w2img[0][0][0], tid);
    stage16k(w1addr[1], &g_w1img[0][1][0], tid);

    // stage params
    for (int i = tid; i < 128; i += THREADS){
        par[i]        = bo_time[i]; par[128 + i]  = bo_recv[i];
        par[256 + i]  = g1[i];      par[384 + i]  = be1[i];
        par[512 + i]  = g2[i];      par[640 + i]  = be2[i];
        par[768 + i]  = g3[i];      par[896 + i]  = be3[i];
        par[1024 + i] = g4[i];      par[1152 + i] = be4[i];
        par[1280 + i] = b2a[i];     par[1408 + i] = b2b[i];
    }
    for (int i = tid; i < 512; i += THREADS){
        par[1536 + i] = b1a[i];     par[2048 + i] = b1b[i];
    }
    __syncthreads();

    // ---- LN1: v1 = LN(x + bo_time) -> sV (fp32) + sVb (bf16), 2 thr/row ----
    const size_t grow = (size_t)blockIdx.x * TILE_R + lrow;
    {
        float4 v[16];
        float s = 0.f, q = 0.f;
#pragma unroll
        for (int i = 0; i < 16; ++i){
            int c = lhalf * 64 + 4 * i;
            float4 a = *(const float4*)(x + grow * 128 + c);
            a.x += par[c + 0]; a.y += par[c + 1]; a.z += par[c + 2]; a.w += par[c + 3];
            v[i] = a;
            s += a.x + a.y + a.z + a.w;
            q = fmaf(a.x, a.x, q); q = fmaf(a.y, a.y, q);
            q = fmaf(a.z, a.z, q); q = fmaf(a.w, a.w, q);
        }
        s += __shfl_xor_sync(0xffffffffu, s, 1, 2);
        q += __shfl_xor_sync(0xffffffffu, q, 1, 2);
        float mu = s * 0.0078125f;
        float rs = rsqrtf(q * 0.0078125f - mu * mu + 1e-5f);
#pragma unroll
        for (int i = 0; i < 16; ++i){
            int c = lhalf * 64 + 4 * i;
            float4 a = v[i], o;
            o.x = (a.x - mu) * rs * par[256 + c + 0] + par[384 + c + 0];
            o.y = (a.y - mu) * rs * par[256 + c + 1] + par[384 + c + 1];
            o.z = (a.z - mu) * rs * par[256 + c + 2] + par[384 + c + 2];
            o.w = (a.w - mu) * rs * par[256 + c + 3] + par[384 + c + 3];
            *(float4*)(sV + lrow * VSTR + c) = o;
            sVb[lrow * VBSTR + (c >> 1)]     = bf2(o.x, o.y);
            sVb[lrow * VBSTR + (c >> 1) + 1] = bf2(o.z, o.w);
        }
    }

    float acc2[2][8][4];
#pragma unroll
    for (int a = 0; a < 2; ++a)
#pragma unroll
        for (int b = 0; b < 8; ++b)
#pragma unroll
            for (int d = 0; d < 4; ++d) acc2[a][b][d] = 0.f;

    uint32_t Afr[2][8][4];   // GEMM1 A operand, register-resident per MLP

    // ---- preamble: GEMM1[0] + epilogue -> sH[0] ----
    CP_WAIT(2);          // W1[0] resident
    __syncthreads();     // sVb visible
    load_afrags(Afr, a1ad);
    {
        float acc1[2][4][4];
        gemm12(acc1, acc2, Afr, a2ad[0], w1buf[0], w2buf[0], wc, lane, false);
        epi1(acc1, sHbuf[0], par + 1536, wr, wc, qrow, qcol);
    }

    // ---- 16 phases: phase p runs GEMM1[p+1] fused with GEMM2[p] ----
    for (int p = 0; p < 16; ++p){
        __syncthreads();   // sH[p&1] writes visible; frees weight buffers
        if (p <= 14) stage16k(w2addr[(p + 1) & 1], &g_w2img[(p + 1) >> 3][(p + 1) & 7][0], tid);
        if (p <= 13) stage16k(w1addr[p & 1],       &g_w1img[(p + 2) >> 3][(p + 2) & 7][0], tid);
        if (p <= 13)      CP_WAIT(2);
        else if (p == 14) CP_WAIT(1);
        else              CP_WAIT(0);

        const int ch = p & 7;
        if (ch != 7){
            const int q = p + 1;
            float acc1[2][4][4];
            gemm12(acc1, acc2, Afr, a2ad[p & 1], w1buf[q & 1], w2buf[p & 1],
                   wc, lane, true);
            epi1(acc1, sHbuf[q & 1],
                 par + ((q >= 8) ? 2048 : 1536) + (q & 7) * 64, wr, wc, qrow, qcol);
        } else {
            // boundary: finish this MLP, run LN chain, then start next MLP's GEMM1
            gemm2_only(acc2, a2ad[1], w2buf[1], wc, lane);
            const float* pB2 = par + ((p >= 8) ? 1408 : 1280);
            // T = V + D2 + b2, in place in sV (warp tile 32x64)
#pragma unroll
            for (int mt = 0; mt < 2; ++mt){
                const int rb = wr * 32 + mt * 16 + qrow;
#pragma unroll
                for (int ntl = 0; ntl < 8; ++ntl){
                    const int cb = wc * 64 + ntl * 8 + 2 * qcol;
                    const float b20 = pB2[cb], b21 = pB2[cb + 1];
                    float2* v0p = (float2*)(sV + rb * VSTR + cb);
                    float2* v1p = (float2*)(sV + (rb + 8) * VSTR + cb);
                    float2 v0 = *v0p, v1 = *v1p;
                    v0.x += acc2[mt][ntl][0] + b20; v0.y += acc2[mt][ntl][1] + b21;
                    v1.x += acc2[mt][ntl][2] + b20; v1.y += acc2[mt][ntl][3] + b21;
                    *v0p = v0; *v1p = v1;
                }
            }
            __syncthreads();

            // LN on T rows (2 threads/row)
            float4 v[16];
            float s = 0.f, q = 0.f;
#pragma unroll
            for (int i = 0; i < 16; ++i){
                int c = lhalf * 64 + 4 * i;
                float4 a = *(const float4*)(sV + lrow * VSTR + c);
                v[i] = a;
                s += a.x + a.y + a.z + a.w;
                q = fmaf(a.x, a.x, q); q = fmaf(a.y, a.y, q);
                q = fmaf(a.z, a.z, q); q = fmaf(a.w, a.w, q);
            }
            s += __shfl_xor_sync(0xffffffffu, s, 1, 2);
            q += __shfl_xor_sync(0xffffffffu, q, 1, 2);
            float mu = s * 0.0078125f;
            float rs = rsqrtf(q * 0.0078125f - mu * mu + 1e-5f);

            if (p == 7){
                // v2 = LN2(T); v3 = LN3(v2 + bo_recv) -> sV + sVb
                float s2 = 0.f, q2 = 0.f;
#pragma unroll
                for (int i = 0; i < 16; ++i){
                    int c = lhalf * 64 + 4 * i;
                    float4 a = v[i], o;
                    o.x = (a.x - mu) * rs * par[512 + c + 0] + par[640 + c + 0] + par[128 + c + 0];
                    o.y = (a.y - mu) * rs * par[512 + c + 1] + par[640 + c + 1] + par[128 + c + 1];
                    o.z = (a.z - mu) * rs * par[512 + c + 2] + par[640 + c + 2] + par[128 + c + 2];
                    o.w = (a.w - mu) * rs * par[512 + c + 3] + par[640 + c + 3] + par[128 + c + 3];
                    v[i] = o;
                    s2 += o.x + o.y + o.z + o.w;
                    q2 = fmaf(o.x, o.x, q2); q2 = fmaf(o.y, o.y, q2);
                    q2 = fmaf(o.z, o.z, q2); q2 = fmaf(o.w, o.w, q2);
                }
                s2 += __shfl_xor_sync(0xffffffffu, s2, 1, 2);
                q2 += __shfl_xor_sync(0xffffffffu, q2, 1, 2);
                float mu2 = s2 * 0.0078125f;
                float rs2 = rsqrtf(q2 * 0.0078125f - mu2 * mu2 + 1e-5f);
#pragma unroll
                for (int i = 0; i < 16; ++i){
                    int c = lhalf * 64 + 4 * i;
                    float4 a = v[i], o;
                    o.x = (a.x - mu2) * rs2 * par[768 + c + 0] + par[896 + c + 0];
                    o.y = (a.y - mu2) * rs2 * par[768 + c + 1] + par[896 + c + 1];
                    o.z = (a.z - mu2) * rs2 * par[768 + c + 2] + par[896 + c + 2];
                    o.w = (a.w - mu2) * rs2 * par[768 + c + 3] + par[896 + c + 3];
                    *(float4*)(sV + lrow * VSTR + c) = o;
                    sVb[lrow * VBSTR + (c >> 1)]     = bf2(o.x, o.y);
                    sVb[lrow * VBSTR + (c >> 1) + 1] = bf2(o.z, o.w);
                }
                __syncthreads();   // sVb ready for mlp1's GEMM1

#pragma unroll
                for (int a = 0; a < 2; ++a)
#pragma unroll
                    for (int b = 0; b < 8; ++b)
#pragma unroll
                        for (int d = 0; d < 4; ++d) acc2[a][b][d] = 0.f;
                load_afrags(Afr, a1ad);   // new V -> reload resident A
                float acc1[2][4][4];
                gemm12(acc1, acc2, Afr, a2ad[0], w1buf[0], w2buf[0], wc, lane, false);
                epi1(acc1, sHbuf[0], par + 2048, wr, wc, qrow, qcol);
            } else {
                // p == 15: out = LN4(T) -> GMEM
#pragma unroll
                for (int i = 0; i < 16; ++i){
                    int c = lhalf * 64 + 4 * i;
                    float4 a = v[i], o;
                    o.x = (a.x - mu) * rs * par[1024 + c + 0] + par[1152 + c + 0];
                    o.y = (a.y - mu) * rs * par[1024 + c + 1] + par[1152 + c + 1];
                    o.z = (a.z - mu) * rs * par[1024 + c + 2] + par[1152 + c + 2];
                    o.w = (a.w - mu) * rs * par[1024 + c + 3] + par[1152 + c + 3];
                    *(float4*)(out + grow * 128 + c) = o;
                }
            }
        }
    }
}

extern "C" void kernel_launch(void* const* d_in, const int* in_sizes, int n_in,
                              void* d_out, int out_size)
{
    const float* x       = (const float*)d_in[0];
    // d_in[1]=router (dead), d_in[3]=bo_send (dead)
    const float* bo_time = (const float*)d_in[2];
    const float* bo_recv = (const float*)d_in[4];
    const float* g1 = (const float*)d_in[5],  *be1 = (const float*)d_in[6];
    const float* g2 = (const float*)d_in[7],  *be2 = (const float*)d_in[8];
    const float* g3 = (const float*)d_in[9],  *be3 = (const float*)d_in[10];
    const float* g4 = (const float*)d_in[11], *be4 = (const float*)d_in[12];
    const float* W1a = (const float*)d_in[13], *b1a = (const float*)d_in[14];
    const float* W2a = (const float*)d_in[15], *b2a = (const float*)d_in[16];
    const float* W1b = (const float*)d_in[17], *b1b = (const float*)d_in[18];
    const float* W2b = (const float*)d_in[19], *b2b = (const float*)d_in[20];
    float* out = (float*)d_out;

    int rows   = in_sizes[0] / 128;   // 131072
    int blocks = rows / TILE_R;       // 1024

    prep_kernel<<<128, 256>>>(W1a, W2a, W1b, W2b);

    cudaFuncSetAttribute(tsal_big_kernel,
                         cudaFuncAttributeMaxDynamicSharedMemorySize, SMEM_BYTES);
    tsal_big_kernel<<<blocks, THREADS, SMEM_BYTES>>>(
        x, bo_time, bo_recv,
        g1, be1, g2, be2, g3, be3, g4, be4,
        b1a, b2a, b1b, b2b, out);
}